// round 16
// baseline (speedup 1.0000x reference)
#include <cuda_runtime.h>
#include <cuda_bf16.h>
#include <mma.h>
#include <cstdint>
#include <cstddef>

using namespace nvcuda;

// Problem constants (fixed by the dataset)
#define MAXN   50000
#define MAXE   800000
#define INDIM  128
#define HID    256
#define NB     64
#define T_     4
#define G_     4

// ---------------- scratch (static device globals; no allocation) -------------
__device__ int   g_deg[MAXN];
__device__ int   g_off[MAXN + 1];
__device__ int   g_cursor[MAXN];
__device__ int   g_partial[512];
__device__ int   g_csr_src[MAXE];
__device__ float g_csr_w[MAXE];
__device__ float g_dinv[MAXN];
__device__ __nv_bfloat16 g_m2b[(size_t)MAXN * HID];       // m2 bf16 (25.6 MB)
__device__ __nv_bfloat16 g_ah[(size_t)MAXN * HID];        // layer-1 GEMM in hi
__device__ __nv_bfloat16 g_al[(size_t)MAXN * HID];        // layer-1 GEMM in lo
__device__ __nv_bfloat16 g_ah2[(size_t)MAXN * HID];       // layer-2 GEMM in hi
__device__ __nv_bfloat16 g_al2[(size_t)MAXN * HID];       // layer-2 GEMM in lo
__device__ __nv_bfloat16 g_wh1[INDIM * HID];
__device__ __nv_bfloat16 g_wl1[INDIM * HID];
__device__ __nv_bfloat16 g_wh2[HID * HID];
__device__ __nv_bfloat16 g_wl2[HID * HID];
__device__ float g_gsum[NB * HID];
__device__ float g_gcnt[NB];

// ---------------- CSR build ---------------------------------------------------
__global__ void k_zero_deg(int* deg, int n) {
    int i = blockIdx.x * blockDim.x + threadIdx.x;
    if (i < n) deg[i] = 0;
}

__global__ void k_count_deg(const int* __restrict__ dst, int* deg, int E) {
    int e = blockIdx.x * blockDim.x + threadIdx.x;
    if (e < E) atomicAdd(&deg[dst[e]], 1);
}

__global__ void k_scan1(const int* __restrict__ deg, int* off, int* partial, int n) {
    __shared__ int sh[256];
    int i = blockIdx.x * 256 + threadIdx.x;
    int v = (i < n) ? deg[i] : 0;
    sh[threadIdx.x] = v;
    __syncthreads();
    for (int s = 1; s < 256; s <<= 1) {
        int t = (threadIdx.x >= s) ? sh[threadIdx.x - s] : 0;
        __syncthreads();
        sh[threadIdx.x] += t;
        __syncthreads();
    }
    if (i < n) off[i] = sh[threadIdx.x] - v;
    if (threadIdx.x == 255) partial[blockIdx.x] = sh[255];
}

__global__ void k_scan2(int* partial, int nb) {
    __shared__ int sh[256];
    int v = (threadIdx.x < nb) ? partial[threadIdx.x] : 0;
    sh[threadIdx.x] = v;
    __syncthreads();
    for (int s = 1; s < 256; s <<= 1) {
        int t = (threadIdx.x >= s) ? sh[threadIdx.x - s] : 0;
        __syncthreads();
        sh[threadIdx.x] += t;
        __syncthreads();
    }
    if (threadIdx.x < nb) partial[threadIdx.x] = sh[threadIdx.x] - v;
}

// scan finalize + dinv fused
__global__ void k_scan3(int* off, const int* __restrict__ partial, int* cursor,
                        const int* __restrict__ deg, float* dinv, int n, int E) {
    int i = blockIdx.x * 256 + threadIdx.x;
    if (i < n) {
        int o = off[i] + partial[blockIdx.x];
        off[i] = o;
        cursor[i] = o;
        dinv[i] = rsqrtf((float)deg[i] + 1.0f);
    }
    if (i == 0) off[n] = E;
}

__global__ void k_fill(const int* __restrict__ src, const int* __restrict__ dst,
                       const float* __restrict__ dinv,
                       int* cursor, int* csr, float* csrw, int E) {
    int e = blockIdx.x * blockDim.x + threadIdx.x;
    if (e < E) {
        int s = src[e];
        int pos = atomicAdd(&cursor[dst[e]], 1);
        csr[pos] = s;
        csrw[pos] = __ldg(dinv + s);
    }
}

// ---------------- both weight splits in one kernel ----------------------------
__global__ void k_split_w2(const float* __restrict__ W1, const float* __restrict__ W2,
                           __nv_bfloat16* __restrict__ Wh1, __nv_bfloat16* __restrict__ Wl1,
                           __nv_bfloat16* __restrict__ Wh2, __nv_bfloat16* __restrict__ Wl2) {
    int idx = blockIdx.x * blockDim.x + threadIdx.x;
    const int n1 = INDIM * HID;
    const int n2 = HID * HID;
    if (idx < n1) {
        float w = W1[idx];
        __nv_bfloat16 hi = __float2bfloat16_rn(w);
        Wh1[idx] = hi;
        Wl1[idx] = __float2bfloat16_rn(w - __bfloat162float(hi));
    } else if (idx < n1 + n2) {
        int j = idx - n1;
        float w = W2[j];
        __nv_bfloat16 hi = __float2bfloat16_rn(w);
        Wh2[j] = hi;
        Wl2[j] = __float2bfloat16_rn(w - __bfloat162float(hi));
    }
}

// ---------------- gather (layer 1, W=128) fused with bf16 hi/lo split --------
__global__ __launch_bounds__(128) void k_gather_split128(
        const float* __restrict__ H, const int* __restrict__ csr,
        const float* __restrict__ csrw, const int* __restrict__ off,
        const float* __restrict__ dinv,
        __nv_bfloat16* __restrict__ Ah, __nv_bfloat16* __restrict__ Al, int n) {
    const int node = blockIdx.x * 4 + (threadIdx.x >> 5);
    if (node >= n) return;
    const int c4 = (threadIdx.x & 31) * 4;
    const float di = __ldg(dinv + node);
    float4 h = *(const float4*)(H + (size_t)node * INDIM + c4);
    float ax = h.x * di, ay = h.y * di, az = h.z * di, aw = h.w * di;
    int e = __ldg(off + node);
    const int e1 = __ldg(off + node + 1);
    for (; e + 3 < e1; e += 4) {
        int s0 = __ldg(csr + e);
        int s1 = __ldg(csr + e + 1);
        int s2 = __ldg(csr + e + 2);
        int s3 = __ldg(csr + e + 3);
        float w0 = __ldg(csrw + e);
        float w1 = __ldg(csrw + e + 1);
        float w2 = __ldg(csrw + e + 2);
        float w3 = __ldg(csrw + e + 3);
        float4 v0 = *(const float4*)(H + (size_t)s0 * INDIM + c4);
        float4 v1 = *(const float4*)(H + (size_t)s1 * INDIM + c4);
        float4 v2 = *(const float4*)(H + (size_t)s2 * INDIM + c4);
        float4 v3 = *(const float4*)(H + (size_t)s3 * INDIM + c4);
        ax = fmaf(v0.x, w0, ax); ay = fmaf(v0.y, w0, ay);
        az = fmaf(v0.z, w0, az); aw = fmaf(v0.w, w0, aw);
        ax = fmaf(v1.x, w1, ax); ay = fmaf(v1.y, w1, ay);
        az = fmaf(v1.z, w1, az); aw = fmaf(v1.w, w1, aw);
        ax = fmaf(v2.x, w2, ax); ay = fmaf(v2.y, w2, ay);
        az = fmaf(v2.z, w2, az); aw = fmaf(v2.w, w2, aw);
        ax = fmaf(v3.x, w3, ax); ay = fmaf(v3.y, w3, ay);
        az = fmaf(v3.z, w3, az); aw = fmaf(v3.w, w3, aw);
    }
    for (; e < e1; e++) {
        int s = __ldg(csr + e);
        float w = __ldg(csrw + e);
        float4 v = *(const float4*)(H + (size_t)s * INDIM + c4);
        ax = fmaf(v.x, w, ax); ay = fmaf(v.y, w, ay);
        az = fmaf(v.z, w, az); aw = fmaf(v.w, w, aw);
    }
    ax *= di; ay *= di; az *= di; aw *= di;
    ushort4 hv, lv;
    __nv_bfloat16 t;
    t = __float2bfloat16_rn(ax); hv.x = *(unsigned short*)&t;
    lv.x = *(unsigned short*)&(t = __float2bfloat16_rn(ax - __bfloat162float(t)));
    t = __float2bfloat16_rn(ay); hv.y = *(unsigned short*)&t;
    lv.y = *(unsigned short*)&(t = __float2bfloat16_rn(ay - __bfloat162float(t)));
    t = __float2bfloat16_rn(az); hv.z = *(unsigned short*)&t;
    lv.z = *(unsigned short*)&(t = __float2bfloat16_rn(az - __bfloat162float(t)));
    t = __float2bfloat16_rn(aw); hv.w = *(unsigned short*)&t;
    lv.w = *(unsigned short*)&(t = __float2bfloat16_rn(aw - __bfloat162float(t)));
    *(ushort4*)(Ah + (size_t)node * INDIM + c4) = hv;
    *(ushort4*)(Al + (size_t)node * INDIM + c4) = lv;
}

// ---------------- FUSED layer-2 gather(bf16) + bias + relu + mean-pool -------
// 32 threads per node (8 bf16 channels each = one uint4), 8 groups per block.
__device__ __forceinline__ void unpack8(uint4 v, float* f) {
    const __nv_bfloat162* p = (const __nv_bfloat162*)&v;
#pragma unroll
    for (int i = 0; i < 4; i++) {
        float2 t = __bfloat1622float2(p[i]);
        f[2 * i] = t.x;
        f[2 * i + 1] = t.y;
    }
}

#define GP_CHUNK 32
__global__ __launch_bounds__(256) void k_gather_pool_bf16(
        const __nv_bfloat16* __restrict__ H, const int* __restrict__ csr,
        const float* __restrict__ csrw, const int* __restrict__ off,
        const float* __restrict__ dinv, const float* __restrict__ b2,
        const int* __restrict__ batch,
        float* __restrict__ gsum, float* __restrict__ gcnt, int n) {
    const int g = threadIdx.x >> 5;       // group 0..7
    const int lane = threadIdx.x & 31;
    const int c8 = lane * 8;
    const int node0 = blockIdx.x * GP_CHUNK;
    int nend = node0 + GP_CHUNK;
    if (nend > n) nend = n;
    float bb[8];
    *(float4*)(bb) = *(const float4*)(b2 + c8);
    *(float4*)(bb + 4) = *(const float4*)(b2 + c8 + 4);
    float s[8];
#pragma unroll
    for (int i = 0; i < 8; i++) s[i] = 0.f;
    float cnt = 0.f;
    int curb = -1;
    for (int node = node0 + g; node < nend; node += 8) {
        int b = __ldg(batch + node);
        if (b != curb) {
            if (curb >= 0) {
                float* gp = gsum + curb * HID + c8;
#pragma unroll
                for (int i = 0; i < 8; i++) atomicAdd(gp + i, s[i]);
                if (lane == 0) atomicAdd(&gcnt[curb], cnt);
            }
            curb = b;
#pragma unroll
            for (int i = 0; i < 8; i++) s[i] = 0.f;
            cnt = 0.f;
        }
        const float di = __ldg(dinv + node);
        float a[8];
        unpack8(*(const uint4*)(H + (size_t)node * HID + c8), a);
#pragma unroll
        for (int i = 0; i < 8; i++) a[i] *= di;
        int e = __ldg(off + node);
        const int e1 = __ldg(off + node + 1);
        for (; e + 3 < e1; e += 4) {
            int s0 = __ldg(csr + e);
            int s1 = __ldg(csr + e + 1);
            int s2 = __ldg(csr + e + 2);
            int s3 = __ldg(csr + e + 3);
            float w0 = __ldg(csrw + e);
            float w1 = __ldg(csrw + e + 1);
            float w2 = __ldg(csrw + e + 2);
            float w3 = __ldg(csrw + e + 3);
            uint4 u0 = *(const uint4*)(H + (size_t)s0 * HID + c8);
            uint4 u1 = *(const uint4*)(H + (size_t)s1 * HID + c8);
            uint4 u2 = *(const uint4*)(H + (size_t)s2 * HID + c8);
            uint4 u3 = *(const uint4*)(H + (size_t)s3 * HID + c8);
            float f[8];
            unpack8(u0, f);
#pragma unroll
            for (int i = 0; i < 8; i++) a[i] = fmaf(f[i], w0, a[i]);
            unpack8(u1, f);
#pragma unroll
            for (int i = 0; i < 8; i++) a[i] = fmaf(f[i], w1, a[i]);
            unpack8(u2, f);
#pragma unroll
            for (int i = 0; i < 8; i++) a[i] = fmaf(f[i], w2, a[i]);
            unpack8(u3, f);
#pragma unroll
            for (int i = 0; i < 8; i++) a[i] = fmaf(f[i], w3, a[i]);
        }
        for (; e < e1; e++) {
            int ss = __ldg(csr + e);
            float w = __ldg(csrw + e);
            float f[8];
            unpack8(*(const uint4*)(H + (size_t)ss * HID + c8), f);
#pragma unroll
            for (int i = 0; i < 8; i++) a[i] = fmaf(f[i], w, a[i]);
        }
#pragma unroll
        for (int i = 0; i < 8; i++)
            s[i] += fmaxf(a[i] * di + bb[i], 0.f);
        cnt += 1.f;
    }
    if (curb >= 0) {
        float* gp = gsum + curb * HID + c8;
#pragma unroll
        for (int i = 0; i < 8; i++) atomicAdd(gp + i, s[i]);
        if (lane == 0) atomicAdd(&gcnt[curb], cnt);
    }
}

// ---------------- WMMA bf16 3-product GEMM ------------------------------------
// MODE 1: v = relu(acc + bias); hi/lo split -> Ch/Cl bf16 (vectorized).
// MODE 2: plain bf16 round of acc -> Ch (vectorized).
// BM=128, BN=128, BK=16. 256 threads = 8 warps in 2x4; warp tile 64x32.
#define WG_LDA 40     // padded A stride (80B rows) to break pow-2 conflicts
#define WG_LDB 144

template <int MODE>
__global__ __launch_bounds__(256) void k_wgemm(const __nv_bfloat16* __restrict__ Ah,
                                               const __nv_bfloat16* __restrict__ Al,
                                               const __nv_bfloat16* __restrict__ Bh,
                                               const __nv_bfloat16* __restrict__ Bl,
                                               const float* __restrict__ bias,
                                               __nv_bfloat16* __restrict__ Ch,
                                               __nv_bfloat16* __restrict__ Cl,
                                               int M, int K, int N2) {
    __shared__ __nv_bfloat16 sAh[128 * WG_LDA];
    __shared__ __nv_bfloat16 sAl[128 * WG_LDA];
    __shared__ __nv_bfloat16 sBh[16 * WG_LDB];
    __shared__ __nv_bfloat16 sBl[16 * WG_LDB];
    __shared__ float sC[8][16 * 16];

    const int tid = threadIdx.x;
    const int wid = tid >> 5;
    const int lane = tid & 31;
    const int wm = wid >> 2;
    const int wn = wid & 3;
    const int row0 = blockIdx.y * 128;
    const int col0 = blockIdx.x * 128;

    // per-thread staging coordinates
    const int ar = tid >> 1;                 // A row 0..127
    const int ac = (tid & 1) * 8;            // A col 0 or 8
    const int br = tid >> 4;                 // B row 0..15
    const int bc = (tid & 15) * 8;           // B col 0..120
    const bool arok = (row0 + ar) < M;
    const __nv_bfloat16* Agp = Ah + (size_t)(row0 + ar) * K + ac;
    const __nv_bfloat16* Algp = Al + (size_t)(row0 + ar) * K + ac;
    const __nv_bfloat16* Bgp = Bh + (size_t)br * N2 + col0 + bc;
    const __nv_bfloat16* Blgp = Bl + (size_t)br * N2 + col0 + bc;

    uint4 rAh, rAl, rBh, rBl;

    wmma::fragment<wmma::accumulator, 16, 16, 16, float> acc[4][2];
#pragma unroll
    for (int i = 0; i < 4; i++)
#pragma unroll
        for (int j = 0; j < 2; j++) wmma::fill_fragment(acc[i][j], 0.f);

    // prologue: load tile 0
    rAh = arok ? *(const uint4*)(Agp) : make_uint4(0, 0, 0, 0);
    rAl = arok ? *(const uint4*)(Algp) : make_uint4(0, 0, 0, 0);
    rBh = *(const uint4*)(Bgp);
    rBl = *(const uint4*)(Blgp);
    *(uint4*)(sAh + ar * WG_LDA + ac) = rAh;
    *(uint4*)(sAl + ar * WG_LDA + ac) = rAl;
    *(uint4*)(sBh + br * WG_LDB + bc) = rBh;
    *(uint4*)(sBl + br * WG_LDB + bc) = rBl;
    __syncthreads();

    for (int k0 = 16; k0 <= K; k0 += 16) {
        // stage next tile's global loads (overlap with mma below)
        if (k0 < K) {
            rAh = arok ? *(const uint4*)(Agp + k0) : make_uint4(0, 0, 0, 0);
            rAl = arok ? *(const uint4*)(Algp + k0) : make_uint4(0, 0, 0, 0);
            rBh = *(const uint4*)(Bgp + (size_t)k0 * N2);
            rBl = *(const uint4*)(Blgp + (size_t)k0 * N2);
        }
        // mma on current smem tile
        wmma::fragment<wmma::matrix_b, 16, 16, 16, __nv_bfloat16, wmma::row_major> fbh[2], fbl[2];
#pragma unroll
        for (int j = 0; j < 2; j++) {
            wmma::load_matrix_sync(fbh[j], sBh + wn * 32 + j * 16, WG_LDB);
            wmma::load_matrix_sync(fbl[j], sBl + wn * 32 + j * 16, WG_LDB);
        }
#pragma unroll
        for (int i = 0; i < 4; i++) {
            wmma::fragment<wmma::matrix_a, 16, 16, 16, __nv_bfloat16, wmma::row_major> fah, fal;
            wmma::load_matrix_sync(fah, sAh + (wm * 64 + i * 16) * WG_LDA, WG_LDA);
            wmma::load_matrix_sync(fal, sAl + (wm * 64 + i * 16) * WG_LDA, WG_LDA);
#pragma unroll
            for (int j = 0; j < 2; j++) {
                wmma::mma_sync(acc[i][j], fah, fbh[j], acc[i][j]);
                wmma::mma_sync(acc[i][j], fah, fbl[j], acc[i][j]);
                wmma::mma_sync(acc[i][j], fal, fbh[j], acc[i][j]);
            }
        }
        if (k0 < K) {
            __syncthreads();                     // all warps done reading smem
            *(uint4*)(sAh + ar * WG_LDA + ac) = rAh;
            *(uint4*)(sAl + ar * WG_LDA + ac) = rAl;
            *(uint4*)(sBh + br * WG_LDB + bc) = rBh;
            *(uint4*)(sBl + br * WG_LDB + bc) = rBl;
            __syncthreads();                     // new tile visible
        }
    }

#pragma unroll
    for (int i = 0; i < 4; i++) {
        int r = row0 + wm * 64 + i * 16;
        if (r >= M) continue;
#pragma unroll
        for (int j = 0; j < 2; j++) {
            int c0 = col0 + wn * 32 + j * 16;
            wmma::store_matrix_sync(sC[wid], acc[i][j], 16, wmma::mem_row_major);
            __syncwarp();
            // lane owns row (lane>>1), 8 consecutive cols at (lane&1)*8
            const int er = lane >> 1;
            const int ec0 = (lane & 1) * 8;
            size_t o = (size_t)(r + er) * N2 + c0 + ec0;
            if (MODE == 1) {
                __nv_bfloat16 hbuf[8], lbuf[8];
#pragma unroll
                for (int e = 0; e < 8; e++) {
                    float v = sC[wid][lane * 8 + e] + __ldg(bias + c0 + ec0 + e);
                    v = fmaxf(v, 0.f);
                    __nv_bfloat16 hi = __float2bfloat16_rn(v);
                    hbuf[e] = hi;
                    lbuf[e] = __float2bfloat16_rn(v - __bfloat162float(hi));
                }
                *(uint4*)(Ch + o) = *(uint4*)hbuf;
                *(uint4*)(Cl + o) = *(uint4*)lbuf;
            } else {
                __nv_bfloat16 hbuf[8];
#pragma unroll
                for (int e = 0; e < 8; e++)
                    hbuf[e] = __float2bfloat16_rn(sC[wid][lane * 8 + e]);
                *(uint4*)(Ch + o) = *(uint4*)hbuf;
            }
            __syncwarp();
        }
    }
}

// ---------------- zero pool accumulators ------------------------------------
__global__ void k_zero_pool(float* gsum, float* gcnt) {
    int i = blockIdx.x * blockDim.x + threadIdx.x;
    if (i < NB * HID) gsum[i] = 0.f;
    if (i < NB) gcnt[i] = 0.f;
}

// ---------------- heads: type + per-type grade ------------------------------
__global__ __launch_bounds__(256) void k_heads(const float* __restrict__ tW1,
                                               const float* __restrict__ tb1,
                                               const float* __restrict__ tW2,
                                               const float* __restrict__ tb2,
                                               const float* __restrict__ gW1,
                                               const float* __restrict__ gb1,
                                               const float* __restrict__ gW2,
                                               const float* __restrict__ gb2,
                                               const float* __restrict__ gsum,
                                               const float* __restrict__ gcnt,
                                               float* __restrict__ out) {
    __shared__ float gs[HID];
    __shared__ float z[HID];
    const int b = blockIdx.x;
    const int k = threadIdx.x;

    float cnt = fmaxf(gcnt[b], 1.0f);
    gs[k] = gsum[b * HID + k] / cnt;
    __syncthreads();

    float a = tb1[k];
    for (int h = 0; h < HID; h++) a = fmaf(gs[h], tW1[h * HID + k], a);
    z[k] = fmaxf(a, 0.f);
    __syncthreads();

    if (k < T_) {
        float s = tb2[k];
        for (int j = 0; j < HID; j++) s = fmaf(z[j], tW2[j * T_ + k], s);
        out[b * T_ + k] = s;
    }

    float* gout = out + NB * T_;
    for (int t = 0; t < T_; t++) {
        float h1 = gb1[t * HID + k];
        const float* w1t = gW1 + (size_t)t * HID * HID;
        for (int h = 0; h < HID; h++) h1 = fmaf(gs[h], w1t[h * HID + k], h1);
        __syncthreads();
        z[k] = fmaxf(h1, 0.f);
        __syncthreads();
        if (k < G_) {
            float s = gb2[t * G_ + k];
            const float* w2t = gW2 + (size_t)t * HID * G_;
            for (int j = 0; j < HID; j++) s = fmaf(z[j], w2t[j * G_ + k], s);
            gout[(b * T_ + t) * G_ + k] = s;
        }
        __syncthreads();
    }
}

// ============================================================================
extern "C" void kernel_launch(void* const* d_in, const int* in_sizes, int n_in,
                              void* d_out, int out_size) {
    const float* x    = (const float*)d_in[0];
    const int*   ei   = (const int*)d_in[1];
    const int*   batch= (const int*)d_in[2];
    const float* W1   = (const float*)d_in[3];
    const float* b1   = (const float*)d_in[4];
    const float* W2   = (const float*)d_in[5];
    const float* b2   = (const float*)d_in[6];
    const float* tW1  = (const float*)d_in[7];
    const float* tb1  = (const float*)d_in[8];
    const float* tW2  = (const float*)d_in[9];
    const float* tb2  = (const float*)d_in[10];
    const float* gW1  = (const float*)d_in[11];
    const float* gb1  = (const float*)d_in[12];
    const float* gW2  = (const float*)d_in[13];
    const float* gb2  = (const float*)d_in[14];
    float* out = (float*)d_out;

    const int N = in_sizes[0] / INDIM;
    const int E = in_sizes[1] / 2;
    const int* src = ei;
    const int* dst = ei + E;

    int *deg, *off, *cursor, *partial, *csr;
    float *csrw, *dinv, *gsum, *gcnt;
    __nv_bfloat16 *m2b, *ah, *al, *ah2, *al2, *wh1, *wl1, *wh2, *wl2;
    cudaGetSymbolAddress((void**)&deg, g_deg);
    cudaGetSymbolAddress((void**)&off, g_off);
    cudaGetSymbolAddress((void**)&cursor, g_cursor);
    cudaGetSymbolAddress((void**)&partial, g_partial);
    cudaGetSymbolAddress((void**)&csr, g_csr_src);
    cudaGetSymbolAddress((void**)&csrw, g_csr_w);
    cudaGetSymbolAddress((void**)&dinv, g_dinv);
    cudaGetSymbolAddress((void**)&m2b, g_m2b);
    cudaGetSymbolAddress((void**)&ah, g_ah);
    cudaGetSymbolAddress((void**)&al, g_al);
    cudaGetSymbolAddress((void**)&ah2, g_ah2);
    cudaGetSymbolAddress((void**)&al2, g_al2);
    cudaGetSymbolAddress((void**)&wh1, g_wh1);
    cudaGetSymbolAddress((void**)&wl1, g_wl1);
    cudaGetSymbolAddress((void**)&wh2, g_wh2);
    cudaGetSymbolAddress((void**)&wl2, g_wl2);
    cudaGetSymbolAddress((void**)&gsum, g_gsum);
    cudaGetSymbolAddress((void**)&gcnt, g_gcnt);

    const int TPB = 256;
    const int nScanBlocks = (N + 255) / 256;

    // weight splits + pool zeroing (independent of graph structure)
    k_split_w2<<<(INDIM * HID + HID * HID + TPB - 1) / TPB, TPB>>>(
        W1, W2, wh1, wl1, wh2, wl2);
    k_zero_pool<<<(NB * HID + TPB - 1) / TPB, TPB>>>(gsum, gcnt);

    // 1) CSR build (dst-sorted adjacency) + dinv
    k_zero_deg<<<(N + TPB - 1) / TPB, TPB>>>(deg, N);
    k_count_deg<<<(E + TPB - 1) / TPB, TPB>>>(dst, deg, E);
    k_scan1<<<nScanBlocks, 256>>>(deg, off, partial, N);
    k_scan2<<<1, 256>>>(partial, nScanBlocks);
    k_scan3<<<nScanBlocks, 256>>>(off, partial, cursor, deg, dinv, N, E);
    k_fill<<<(E + TPB - 1) / TPB, TPB>>>(src, dst, dinv, cursor, csr, csrw, E);

    // 2) layer-1 aggregation, fused bf16 split -> ah/al
    k_gather_split128<<<(N + 3) / 4, 128>>>(x, csr, csrw, off, dinv, ah, al, N);

    const dim3 ggrid(HID / 128, (N + 127) / 128);

    // 3) h1 = relu((Ax)@W1 + b1), fused split -> ah2/al2
    k_wgemm<1><<<ggrid, 256>>>(ah, al, wh1, wl1, b1, ah2, al2,
                               N, INDIM, HID);

    // 4) m2 = h1 @ W2 -> m2b bf16 (b2 applied in fused gather-pool)
    k_wgemm<2><<<ggrid, 256>>>(ah2, al2, wh2, wl2, nullptr, m2b, nullptr,
                               N, HID, HID);

    // 5+6) fused layer-2 aggregation (bf16 rows) + bias + relu + mean pool
    k_gather_pool_bf16<<<(N + GP_CHUNK - 1) / GP_CHUNK, 256>>>(
        m2b, csr, csrw, off, dinv, b2, batch, gsum, gcnt, N);

    // 7) heads -> d_out
    k_heads<<<NB, 256>>>(tW1, tb1, tW2, tb2, gW1, gb1, gW2, gb2, gsum, gcnt, out);
}

// round 17
// speedup vs baseline: 1.1038x; 1.1038x over previous
#include <cuda_runtime.h>
#include <cuda_bf16.h>
#include <mma.h>
#include <cstdint>
#include <cstddef>

using namespace nvcuda;

// Problem constants (fixed by the dataset)
#define MAXN   50000
#define MAXE   800000
#define INDIM  128
#define HID    256
#define NB     64
#define T_     4
#define G_     4

// ---------------- scratch (static device globals; no allocation) -------------
__device__ int   g_deg[MAXN];
__device__ int   g_off[MAXN + 1];
__device__ int   g_cursor[MAXN];
__device__ int   g_partial[512];
__device__ int   g_csr_src[MAXE];
__device__ float g_csr_w[MAXE];
__device__ float g_dinv[MAXN];
__device__ float g_bufA[(size_t)MAXN * HID];              // m2 fp32
__device__ __nv_bfloat16 g_ah[(size_t)MAXN * HID];        // layer-1 GEMM in hi
__device__ __nv_bfloat16 g_al[(size_t)MAXN * HID];        // layer-1 GEMM in lo
__device__ __nv_bfloat16 g_ah2[(size_t)MAXN * HID];       // layer-2 GEMM in hi
__device__ __nv_bfloat16 g_al2[(size_t)MAXN * HID];       // layer-2 GEMM in lo
__device__ __nv_bfloat16 g_wh1[INDIM * HID];
__device__ __nv_bfloat16 g_wl1[INDIM * HID];
__device__ __nv_bfloat16 g_wh2[HID * HID];
__device__ __nv_bfloat16 g_wl2[HID * HID];
__device__ float g_gsum[NB * HID];
__device__ float g_gcnt[NB];

// ---------------- fused zero: deg + pool accumulators -------------------------
__global__ void k_zero_all(int* deg, float* gsum, float* gcnt, int n) {
    int i = blockIdx.x * blockDim.x + threadIdx.x;
    if (i < n) deg[i] = 0;
    if (i < NB * HID) gsum[i] = 0.f;
    if (i < NB) gcnt[i] = 0.f;
}

__global__ void k_count_deg(const int* __restrict__ dst, int* deg, int E) {
    int e = blockIdx.x * blockDim.x + threadIdx.x;
    if (e < E) atomicAdd(&deg[dst[e]], 1);
}

__global__ void k_scan1(const int* __restrict__ deg, int* off, int* partial, int n) {
    __shared__ int sh[256];
    int i = blockIdx.x * 256 + threadIdx.x;
    int v = (i < n) ? deg[i] : 0;
    sh[threadIdx.x] = v;
    __syncthreads();
    for (int s = 1; s < 256; s <<= 1) {
        int t = (threadIdx.x >= s) ? sh[threadIdx.x - s] : 0;
        __syncthreads();
        sh[threadIdx.x] += t;
        __syncthreads();
    }
    if (i < n) off[i] = sh[threadIdx.x] - v;
    if (threadIdx.x == 255) partial[blockIdx.x] = sh[255];
}

__global__ void k_scan2(int* partial, int nb) {
    __shared__ int sh[256];
    int v = (threadIdx.x < nb) ? partial[threadIdx.x] : 0;
    sh[threadIdx.x] = v;
    __syncthreads();
    for (int s = 1; s < 256; s <<= 1) {
        int t = (threadIdx.x >= s) ? sh[threadIdx.x - s] : 0;
        __syncthreads();
        sh[threadIdx.x] += t;
        __syncthreads();
    }
    if (threadIdx.x < nb) partial[threadIdx.x] = sh[threadIdx.x] - v;
}

// scan finalize + dinv fused
__global__ void k_scan3(int* off, const int* __restrict__ partial, int* cursor,
                        const int* __restrict__ deg, float* dinv, int n, int E) {
    int i = blockIdx.x * 256 + threadIdx.x;
    if (i < n) {
        int o = off[i] + partial[blockIdx.x];
        off[i] = o;
        cursor[i] = o;
        dinv[i] = rsqrtf((float)deg[i] + 1.0f);
    }
    if (i == 0) off[n] = E;
}

__global__ void k_fill(const int* __restrict__ src, const int* __restrict__ dst,
                       const float* __restrict__ dinv,
                       int* cursor, int* csr, float* csrw, int E) {
    int e = blockIdx.x * blockDim.x + threadIdx.x;
    if (e < E) {
        int s = src[e];
        int pos = atomicAdd(&cursor[dst[e]], 1);
        csr[pos] = s;
        csrw[pos] = __ldg(dinv + s);
    }
}

// ---------------- both weight splits in one kernel ----------------------------
__global__ void k_split_w2(const float* __restrict__ W1, const float* __restrict__ W2,
                           __nv_bfloat16* __restrict__ Wh1, __nv_bfloat16* __restrict__ Wl1,
                           __nv_bfloat16* __restrict__ Wh2, __nv_bfloat16* __restrict__ Wl2) {
    int idx = blockIdx.x * blockDim.x + threadIdx.x;
    const int n1 = INDIM * HID;
    const int n2 = HID * HID;
    if (idx < n1) {
        float w = W1[idx];
        __nv_bfloat16 hi = __float2bfloat16_rn(w);
        Wh1[idx] = hi;
        Wl1[idx] = __float2bfloat16_rn(w - __bfloat162float(hi));
    } else if (idx < n1 + n2) {
        int j = idx - n1;
        float w = W2[j];
        __nv_bfloat16 hi = __float2bfloat16_rn(w);
        Wh2[j] = hi;
        Wl2[j] = __float2bfloat16_rn(w - __bfloat162float(hi));
    }
}

// ---------------- gather (layer 1, W=128) fused with bf16 hi/lo split --------
// 32 threads per node, 4 nodes per block; 4-edge unroll for MLP
__global__ __launch_bounds__(128) void k_gather_split128(
        const float* __restrict__ H, const int* __restrict__ csr,
        const float* __restrict__ csrw, const int* __restrict__ off,
        const float* __restrict__ dinv,
        __nv_bfloat16* __restrict__ Ah, __nv_bfloat16* __restrict__ Al, int n) {
    const int node = blockIdx.x * 4 + (threadIdx.x >> 5);
    if (node >= n) return;
    const int c4 = (threadIdx.x & 31) * 4;
    const float di = __ldg(dinv + node);
    float4 h = *(const float4*)(H + (size_t)node * INDIM + c4);
    float ax = h.x * di, ay = h.y * di, az = h.z * di, aw = h.w * di;
    int e = __ldg(off + node);
    const int e1 = __ldg(off + node + 1);
    for (; e + 3 < e1; e += 4) {
        int s0 = __ldg(csr + e);
        int s1 = __ldg(csr + e + 1);
        int s2 = __ldg(csr + e + 2);
        int s3 = __ldg(csr + e + 3);
        float w0 = __ldg(csrw + e);
        float w1 = __ldg(csrw + e + 1);
        float w2 = __ldg(csrw + e + 2);
        float w3 = __ldg(csrw + e + 3);
        float4 v0 = *(const float4*)(H + (size_t)s0 * INDIM + c4);
        float4 v1 = *(const float4*)(H + (size_t)s1 * INDIM + c4);
        float4 v2 = *(const float4*)(H + (size_t)s2 * INDIM + c4);
        float4 v3 = *(const float4*)(H + (size_t)s3 * INDIM + c4);
        ax = fmaf(v0.x, w0, ax); ay = fmaf(v0.y, w0, ay);
        az = fmaf(v0.z, w0, az); aw = fmaf(v0.w, w0, aw);
        ax = fmaf(v1.x, w1, ax); ay = fmaf(v1.y, w1, ay);
        az = fmaf(v1.z, w1, az); aw = fmaf(v1.w, w1, aw);
        ax = fmaf(v2.x, w2, ax); ay = fmaf(v2.y, w2, ay);
        az = fmaf(v2.z, w2, az); aw = fmaf(v2.w, w2, aw);
        ax = fmaf(v3.x, w3, ax); ay = fmaf(v3.y, w3, ay);
        az = fmaf(v3.z, w3, az); aw = fmaf(v3.w, w3, aw);
    }
    for (; e < e1; e++) {
        int s = __ldg(csr + e);
        float w = __ldg(csrw + e);
        float4 v = *(const float4*)(H + (size_t)s * INDIM + c4);
        ax = fmaf(v.x, w, ax); ay = fmaf(v.y, w, ay);
        az = fmaf(v.z, w, az); aw = fmaf(v.w, w, aw);
    }
    ax *= di; ay *= di; az *= di; aw *= di;
    ushort4 hv, lv;
    __nv_bfloat16 t;
    t = __float2bfloat16_rn(ax); hv.x = *(unsigned short*)&t;
    lv.x = *(unsigned short*)&(t = __float2bfloat16_rn(ax - __bfloat162float(t)));
    t = __float2bfloat16_rn(ay); hv.y = *(unsigned short*)&t;
    lv.y = *(unsigned short*)&(t = __float2bfloat16_rn(ay - __bfloat162float(t)));
    t = __float2bfloat16_rn(az); hv.z = *(unsigned short*)&t;
    lv.z = *(unsigned short*)&(t = __float2bfloat16_rn(az - __bfloat162float(t)));
    t = __float2bfloat16_rn(aw); hv.w = *(unsigned short*)&t;
    lv.w = *(unsigned short*)&(t = __float2bfloat16_rn(aw - __bfloat162float(t)));
    *(ushort4*)(Ah + (size_t)node * INDIM + c4) = hv;
    *(ushort4*)(Al + (size_t)node * INDIM + c4) = lv;
}

// ---------------- FUSED layer-2 gather + bias + relu + mean-pool --------------
// 64 threads per node, 4 groups per block; 4-edge unroll for MLP
#define GP_CHUNK 32
__global__ __launch_bounds__(256) void k_gather_pool(
        const float* __restrict__ H, const int* __restrict__ csr,
        const float* __restrict__ csrw, const int* __restrict__ off,
        const float* __restrict__ dinv, const float* __restrict__ b2,
        const int* __restrict__ batch,
        float* __restrict__ gsum, float* __restrict__ gcnt, int n) {
    const int g = threadIdx.x >> 6;
    const int t = threadIdx.x & 63;
    const int c4 = t * 4;
    const int node0 = blockIdx.x * GP_CHUNK;
    int nend = node0 + GP_CHUNK;
    if (nend > n) nend = n;
    float4 bb = *(const float4*)(b2 + c4);
    float sx = 0.f, sy = 0.f, sz = 0.f, sw = 0.f;
    float cnt = 0.f;
    int curb = -1;
    for (int node = node0 + g; node < nend; node += 4) {
        int b = __ldg(batch + node);
        if (b != curb) {
            if (curb >= 0) {
                float* gp = gsum + curb * HID + c4;
                atomicAdd(gp + 0, sx); atomicAdd(gp + 1, sy);
                atomicAdd(gp + 2, sz); atomicAdd(gp + 3, sw);
                if (t == 0) atomicAdd(&gcnt[curb], cnt);
            }
            curb = b; sx = sy = sz = sw = 0.f; cnt = 0.f;
        }
        const float di = __ldg(dinv + node);
        float4 h = *(const float4*)(H + (size_t)node * HID + c4);
        float ax = h.x * di, ay = h.y * di, az = h.z * di, aw = h.w * di;
        int e = __ldg(off + node);
        const int e1 = __ldg(off + node + 1);
        for (; e + 3 < e1; e += 4) {
            int s0 = __ldg(csr + e);
            int s1 = __ldg(csr + e + 1);
            int s2 = __ldg(csr + e + 2);
            int s3 = __ldg(csr + e + 3);
            float w0 = __ldg(csrw + e);
            float w1 = __ldg(csrw + e + 1);
            float w2 = __ldg(csrw + e + 2);
            float w3 = __ldg(csrw + e + 3);
            float4 v0 = *(const float4*)(H + (size_t)s0 * HID + c4);
            float4 v1 = *(const float4*)(H + (size_t)s1 * HID + c4);
            float4 v2 = *(const float4*)(H + (size_t)s2 * HID + c4);
            float4 v3 = *(const float4*)(H + (size_t)s3 * HID + c4);
            ax = fmaf(v0.x, w0, ax); ay = fmaf(v0.y, w0, ay);
            az = fmaf(v0.z, w0, az); aw = fmaf(v0.w, w0, aw);
            ax = fmaf(v1.x, w1, ax); ay = fmaf(v1.y, w1, ay);
            az = fmaf(v1.z, w1, az); aw = fmaf(v1.w, w1, aw);
            ax = fmaf(v2.x, w2, ax); ay = fmaf(v2.y, w2, ay);
            az = fmaf(v2.z, w2, az); aw = fmaf(v2.w, w2, aw);
            ax = fmaf(v3.x, w3, ax); ay = fmaf(v3.y, w3, ay);
            az = fmaf(v3.z, w3, az); aw = fmaf(v3.w, w3, aw);
        }
        for (; e < e1; e++) {
            int s = __ldg(csr + e);
            float w = __ldg(csrw + e);
            float4 v = *(const float4*)(H + (size_t)s * HID + c4);
            ax = fmaf(v.x, w, ax); ay = fmaf(v.y, w, ay);
            az = fmaf(v.z, w, az); aw = fmaf(v.w, w, aw);
        }
        sx += fmaxf(fmaf(ax, di, 0.f) + bb.x, 0.f);
        sy += fmaxf(fmaf(ay, di, 0.f) + bb.y, 0.f);
        sz += fmaxf(fmaf(az, di, 0.f) + bb.z, 0.f);
        sw += fmaxf(fmaf(aw, di, 0.f) + bb.w, 0.f);
        cnt += 1.f;
    }
    if (curb >= 0) {
        float* gp = gsum + curb * HID + c4;
        atomicAdd(gp + 0, sx); atomicAdd(gp + 1, sy);
        atomicAdd(gp + 2, sz); atomicAdd(gp + 3, sw);
        if (t == 0) atomicAdd(&gcnt[curb], cnt);
    }
}

// ---------------- WMMA bf16 3-product GEMM (R14/R15 proven version) ----------
// MODE 0: store fp32 C.  MODE 1: v = relu(acc + bias); split -> Ch/Cl bf16
// with vectorized uint4 stores (each lane owns 8 consecutive bf16).
// BM=128, BN=128, BK=16. 256 threads = 8 warps in 2x4; warp tile 64x32.
#define WG_LDA 40     // padded A stride (80B rows) to break pow-2 conflicts
#define WG_LDB 144

template <int MODE>
__global__ __launch_bounds__(256) void k_wgemm(const __nv_bfloat16* __restrict__ Ah,
                                               const __nv_bfloat16* __restrict__ Al,
                                               const __nv_bfloat16* __restrict__ Bh,
                                               const __nv_bfloat16* __restrict__ Bl,
                                               const float* __restrict__ bias,
                                               float* __restrict__ Cf,
                                               __nv_bfloat16* __restrict__ Ch,
                                               __nv_bfloat16* __restrict__ Cl,
                                               int M, int K, int N2) {
    __shared__ __nv_bfloat16 sAh[128 * WG_LDA];
    __shared__ __nv_bfloat16 sAl[128 * WG_LDA];
    __shared__ __nv_bfloat16 sBh[16 * WG_LDB];
    __shared__ __nv_bfloat16 sBl[16 * WG_LDB];
    __shared__ float sC[8][16 * 16];

    const int tid = threadIdx.x;
    const int wid = tid >> 5;
    const int lane = tid & 31;
    const int wm = wid >> 2;
    const int wn = wid & 3;
    const int row0 = blockIdx.y * 128;
    const int col0 = blockIdx.x * 128;

    // per-thread staging coordinates
    const int ar = tid >> 1;                 // A row 0..127
    const int ac = (tid & 1) * 8;            // A col 0 or 8
    const int br = tid >> 4;                 // B row 0..15
    const int bc = (tid & 15) * 8;           // B col 0..120
    const bool arok = (row0 + ar) < M;
    const __nv_bfloat16* Agp = Ah + (size_t)(row0 + ar) * K + ac;
    const __nv_bfloat16* Algp = Al + (size_t)(row0 + ar) * K + ac;
    const __nv_bfloat16* Bgp = Bh + (size_t)br * N2 + col0 + bc;
    const __nv_bfloat16* Blgp = Bl + (size_t)br * N2 + col0 + bc;

    uint4 rAh, rAl, rBh, rBl;

    wmma::fragment<wmma::accumulator, 16, 16, 16, float> acc[4][2];
#pragma unroll
    for (int i = 0; i < 4; i++)
#pragma unroll
        for (int j = 0; j < 2; j++) wmma::fill_fragment(acc[i][j], 0.f);

    // prologue: load tile 0
    rAh = arok ? *(const uint4*)(Agp) : make_uint4(0, 0, 0, 0);
    rAl = arok ? *(const uint4*)(Algp) : make_uint4(0, 0, 0, 0);
    rBh = *(const uint4*)(Bgp);
    rBl = *(const uint4*)(Blgp);
    *(uint4*)(sAh + ar * WG_LDA + ac) = rAh;
    *(uint4*)(sAl + ar * WG_LDA + ac) = rAl;
    *(uint4*)(sBh + br * WG_LDB + bc) = rBh;
    *(uint4*)(sBl + br * WG_LDB + bc) = rBl;
    __syncthreads();

    for (int k0 = 16; k0 <= K; k0 += 16) {
        // stage next tile's global loads (overlap with mma below)
        if (k0 < K) {
            rAh = arok ? *(const uint4*)(Agp + k0) : make_uint4(0, 0, 0, 0);
            rAl = arok ? *(const uint4*)(Algp + k0) : make_uint4(0, 0, 0, 0);
            rBh = *(const uint4*)(Bgp + (size_t)k0 * N2);
            rBl = *(const uint4*)(Blgp + (size_t)k0 * N2);
        }
        // mma on current smem tile
        wmma::fragment<wmma::matrix_b, 16, 16, 16, __nv_bfloat16, wmma::row_major> fbh[2], fbl[2];
#pragma unroll
        for (int j = 0; j < 2; j++) {
            wmma::load_matrix_sync(fbh[j], sBh + wn * 32 + j * 16, WG_LDB);
            wmma::load_matrix_sync(fbl[j], sBl + wn * 32 + j * 16, WG_LDB);
        }
#pragma unroll
        for (int i = 0; i < 4; i++) {
            wmma::fragment<wmma::matrix_a, 16, 16, 16, __nv_bfloat16, wmma::row_major> fah, fal;
            wmma::load_matrix_sync(fah, sAh + (wm * 64 + i * 16) * WG_LDA, WG_LDA);
            wmma::load_matrix_sync(fal, sAl + (wm * 64 + i * 16) * WG_LDA, WG_LDA);
#pragma unroll
            for (int j = 0; j < 2; j++) {
                wmma::mma_sync(acc[i][j], fah, fbh[j], acc[i][j]);
                wmma::mma_sync(acc[i][j], fah, fbl[j], acc[i][j]);
                wmma::mma_sync(acc[i][j], fal, fbh[j], acc[i][j]);
            }
        }
        if (k0 < K) {
            __syncthreads();                     // all warps done reading smem
            *(uint4*)(sAh + ar * WG_LDA + ac) = rAh;
            *(uint4*)(sAl + ar * WG_LDA + ac) = rAl;
            *(uint4*)(sBh + br * WG_LDB + bc) = rBh;
            *(uint4*)(sBl + br * WG_LDB + bc) = rBl;
            __syncthreads();                     // new tile visible
        }
    }

#pragma unroll
    for (int i = 0; i < 4; i++) {
        int r = row0 + wm * 64 + i * 16;
        if (r >= M) continue;
#pragma unroll
        for (int j = 0; j < 2; j++) {
            int c0 = col0 + wn * 32 + j * 16;
            if (MODE == 0) {
                wmma::store_matrix_sync(Cf + (size_t)r * N2 + c0, acc[i][j], N2,
                                        wmma::mem_row_major);
            } else {
                wmma::store_matrix_sync(sC[wid], acc[i][j], 16, wmma::mem_row_major);
                __syncwarp();
                // lane owns row (lane>>1), 8 consecutive cols at (lane&1)*8
                const int er = lane >> 1;
                const int ec0 = (lane & 1) * 8;
                __nv_bfloat16 hbuf[8], lbuf[8];
#pragma unroll
                for (int e = 0; e < 8; e++) {
                    float v = sC[wid][lane * 8 + e] + __ldg(bias + c0 + ec0 + e);
                    v = fmaxf(v, 0.f);
                    __nv_bfloat16 hi = __float2bfloat16_rn(v);
                    hbuf[e] = hi;
                    lbuf[e] = __float2bfloat16_rn(v - __bfloat162float(hi));
                }
                size_t o = (size_t)(r + er) * N2 + c0 + ec0;
                *(uint4*)(Ch + o) = *(uint4*)hbuf;
                *(uint4*)(Cl + o) = *(uint4*)lbuf;
                __syncwarp();
            }
        }
    }
}

// ---------------- heads: type + per-type grade ------------------------------
__global__ __launch_bounds__(256) void k_heads(const float* __restrict__ tW1,
                                               const float* __restrict__ tb1,
                                               const float* __restrict__ tW2,
                                               const float* __restrict__ tb2,
                                               const float* __restrict__ gW1,
                                               const float* __restrict__ gb1,
                                               const float* __restrict__ gW2,
                                               const float* __restrict__ gb2,
                                               const float* __restrict__ gsum,
                                               const float* __restrict__ gcnt,
                                               float* __restrict__ out) {
    __shared__ float gs[HID];
    __shared__ float z[HID];
    const int b = blockIdx.x;
    const int k = threadIdx.x;

    float cnt = fmaxf(gcnt[b], 1.0f);
    gs[k] = gsum[b * HID + k] / cnt;
    __syncthreads();

    float a = tb1[k];
    for (int h = 0; h < HID; h++) a = fmaf(gs[h], tW1[h * HID + k], a);
    z[k] = fmaxf(a, 0.f);
    __syncthreads();

    if (k < T_) {
        float s = tb2[k];
        for (int j = 0; j < HID; j++) s = fmaf(z[j], tW2[j * T_ + k], s);
        out[b * T_ + k] = s;
    }

    float* gout = out + NB * T_;
    for (int t = 0; t < T_; t++) {
        float h1 = gb1[t * HID + k];
        const float* w1t = gW1 + (size_t)t * HID * HID;
        for (int h = 0; h < HID; h++) h1 = fmaf(gs[h], w1t[h * HID + k], h1);
        __syncthreads();
        z[k] = fmaxf(h1, 0.f);
        __syncthreads();
        if (k < G_) {
            float s = gb2[t * G_ + k];
            const float* w2t = gW2 + (size_t)t * HID * G_;
            for (int j = 0; j < HID; j++) s = fmaf(z[j], w2t[j * G_ + k], s);
            gout[(b * T_ + t) * G_ + k] = s;
        }
        __syncthreads();
    }
}

// ============================================================================
extern "C" void kernel_launch(void* const* d_in, const int* in_sizes, int n_in,
                              void* d_out, int out_size) {
    const float* x    = (const float*)d_in[0];
    const int*   ei   = (const int*)d_in[1];
    const int*   batch= (const int*)d_in[2];
    const float* W1   = (const float*)d_in[3];
    const float* b1   = (const float*)d_in[4];
    const float* W2   = (const float*)d_in[5];
    const float* b2   = (const float*)d_in[6];
    const float* tW1  = (const float*)d_in[7];
    const float* tb1  = (const float*)d_in[8];
    const float* tW2  = (const float*)d_in[9];
    const float* tb2  = (const float*)d_in[10];
    const float* gW1  = (const float*)d_in[11];
    const float* gb1  = (const float*)d_in[12];
    const float* gW2  = (const float*)d_in[13];
    const float* gb2  = (const float*)d_in[14];
    float* out = (float*)d_out;

    const int N = in_sizes[0] / INDIM;
    const int E = in_sizes[1] / 2;
    const int* src = ei;
    const int* dst = ei + E;

    int *deg, *off, *cursor, *partial, *csr;
    float *csrw, *dinv, *bufA, *gsum, *gcnt;
    __nv_bfloat16 *ah, *al, *ah2, *al2, *wh1, *wl1, *wh2, *wl2;
    cudaGetSymbolAddress((void**)&deg, g_deg);
    cudaGetSymbolAddress((void**)&off, g_off);
    cudaGetSymbolAddress((void**)&cursor, g_cursor);
    cudaGetSymbolAddress((void**)&partial, g_partial);
    cudaGetSymbolAddress((void**)&csr, g_csr_src);
    cudaGetSymbolAddress((void**)&csrw, g_csr_w);
    cudaGetSymbolAddress((void**)&dinv, g_dinv);
    cudaGetSymbolAddress((void**)&bufA, g_bufA);
    cudaGetSymbolAddress((void**)&ah, g_ah);
    cudaGetSymbolAddress((void**)&al, g_al);
    cudaGetSymbolAddress((void**)&ah2, g_ah2);
    cudaGetSymbolAddress((void**)&al2, g_al2);
    cudaGetSymbolAddress((void**)&wh1, g_wh1);
    cudaGetSymbolAddress((void**)&wl1, g_wl1);
    cudaGetSymbolAddress((void**)&wh2, g_wh2);
    cudaGetSymbolAddress((void**)&wl2, g_wl2);
    cudaGetSymbolAddress((void**)&gsum, g_gsum);
    cudaGetSymbolAddress((void**)&gcnt, g_gcnt);

    const int TPB = 256;
    const int nScanBlocks = (N + 255) / 256;

    // weight splits + fused zeroing (independent of graph structure)
    k_split_w2<<<(INDIM * HID + HID * HID + TPB - 1) / TPB, TPB>>>(
        W1, W2, wh1, wl1, wh2, wl2);

    // 1) CSR build (dst-sorted adjacency) + dinv
    k_zero_all<<<(N + TPB - 1) / TPB, TPB>>>(deg, gsum, gcnt, N);
    k_count_deg<<<(E + TPB - 1) / TPB, TPB>>>(dst, deg, E);
    k_scan1<<<nScanBlocks, 256>>>(deg, off, partial, N);
    k_scan2<<<1, 256>>>(partial, nScanBlocks);
    k_scan3<<<nScanBlocks, 256>>>(off, partial, cursor, deg, dinv, N, E);
    k_fill<<<(E + TPB - 1) / TPB, TPB>>>(src, dst, dinv, cursor, csr, csrw, E);

    // 2) layer-1 aggregation, fused bf16 split -> ah/al
    k_gather_split128<<<(N + 3) / 4, 128>>>(x, csr, csrw, off, dinv, ah, al, N);

    const dim3 ggrid(HID / 128, (N + 127) / 128);

    // 3) h1 = relu((Ax)@W1 + b1), fused split -> ah2/al2
    k_wgemm<1><<<ggrid, 256>>>(ah, al, wh1, wl1, b1, nullptr, ah2, al2,
                               N, INDIM, HID);

    // 4) m2 = h1 @ W2 -> bufA fp32 (b2 applied in fused gather-pool)
    k_wgemm<0><<<ggrid, 256>>>(ah2, al2, wh2, wl2, nullptr, bufA, nullptr, nullptr,
                               N, HID, HID);

    // 5+6) fused layer-2 aggregation + bias + relu + mean pool
    k_gather_pool<<<(N + GP_CHUNK - 1) / GP_CHUNK, 256>>>(
        bufA, csr, csrw, off, dinv, b2, batch, gsum, gcnt, N);

    // 7) heads -> d_out
    k_heads<<<NB, 256>>>(tW1, tb1, tW2, tb2, gW1, gb1, gW2, gb2, gsum, gcnt, out);
}